// round 14
// baseline (speedup 1.0000x reference)
#include <cuda_runtime.h>
#include <cuda_fp16.h>
#include <cstdint>

#define Hh 512
#define Ww 512
#define CIN 64
#define KOC 128
#define HWSZ (Hh*Ww)
#define NT 9

#define SWZ(o) ((o) ^ ((((uint32_t)(o))>>3)&0x70))

// ---- dynamic smem layout (100 KB -> 2 CTAs/SM) ----
#define SCL    0
#define SHF    512
#define ABASE  1024
#define AROWS  136
#define ABUFSZ (AROWS*128)                   // 17408
#define ABUF(dy) (ABASE + (dy)*ABUFSZ)       // 3 buffers (dy 0..2), fp16 pixels
#define WGRP   (ABASE + 3*ABUFSZ)            // 53248: single 3-tap W group, 48 KB
#define SMEM_TOTAL (WGRP + 3*16384)          // 102400

__device__ __align__(16) unsigned char Wb[NT*16384];   // pre-swizzled fp16 W tiles

static __device__ __forceinline__ uint32_t s2u(const void* p){
    uint32_t a;
    asm("{ .reg .u64 t; cvta.to.shared.u64 t, %1; cvt.u32.u64 %0, t; }":"=r"(a):"l"(p));
    return a;
}
static __device__ __forceinline__ void ldsm4(uint32_t addr,
        uint32_t &r0, uint32_t &r1, uint32_t &r2, uint32_t &r3){
    asm volatile("ldmatrix.sync.aligned.m8n8.x4.shared.b16 {%0,%1,%2,%3}, [%4];"
        : "=r"(r0),"=r"(r1),"=r"(r2),"=r"(r3) : "r"(addr));
}
static __device__ __forceinline__ void hmma(float* c,
        uint32_t a0,uint32_t a1,uint32_t a2,uint32_t a3,
        uint32_t b0,uint32_t b1){
    asm volatile("mma.sync.aligned.m16n8k16.row.col.f32.f16.f16.f32 "
        "{%0,%1,%2,%3}, {%4,%5,%6,%7}, {%8,%9}, {%0,%1,%2,%3};"
        : "+f"(c[0]),"+f"(c[1]),"+f"(c[2]),"+f"(c[3])
        : "r"(a0),"r"(a1),"r"(a2),"r"(a3),"r"(b0),"r"(b1));
}
static __device__ __forceinline__ void cpasync16(uint32_t daddr, const void* g){
    asm volatile("cp.async.cg.shared.global [%0], [%1], 16;" :: "r"(daddr), "l"(g) : "memory");
}
static __device__ __forceinline__ void cpcommit(){
    asm volatile("cp.async.commit_group;" ::: "memory");
}
template<int N> static __device__ __forceinline__ void cpwait(){
    asm volatile("cp.async.wait_group %0;" :: "n"(N) : "memory");
}

// ---------- prep: W -> fp16, pre-swizzled K-major SW128 tiles (rows = oc) ----------
__global__ void prep_w(const float* __restrict__ Wt){
    int idx = blockIdx.x * blockDim.x + threadIdx.x;   // 9*128*64
    if (idx >= NT*KOC*CIN) return;
    int t   = idx >> 13;
    int rem = idx & 8191;
    int n   = rem >> 6;
    int kk  = rem & 63;
    float v = Wt[(n*CIN + kk)*9 + t];
    uint32_t off = SWZ((uint32_t)(n*128 + kk*2));
    *(__half*)(Wb + t*16384 + off) = __float2half_rn(v);
}

// ---------- main fused kernel: fp16 1-pass, M=oc(128) x N=pix(128), dy-grouped W ----------
__global__ void __launch_bounds__(256,2)
conv_mma_f16(const float* __restrict__ x,
             const float* __restrict__ gamma, const float* __restrict__ beta,
             const float* __restrict__ mean,  const float* __restrict__ var,
             const int*   __restrict__ mask,  float* __restrict__ out)
{
    extern __shared__ __align__(1024) char sm[];
    const uint32_t smb = s2u(sm);

    const int tid  = threadIdx.x;
    const int w    = tid >> 5;
    const int lane = tid & 31;
    const int wpix = w >> 2;           // 0..1 : pixel offset wpix*64 (N dim)
    const int woc  = w & 3;            // 0..3 : oc offset woc*32   (M dim)

    float* s_scale = (float*)(sm + SCL);
    float* s_shift = (float*)(sm + SHF);
    if (tid < KOC) {
        float sc = gamma[tid] * rsqrtf(var[tid] + 1e-5f);
        s_scale[tid] = sc;
        s_shift[tid] = beta[tid] - mean[tid] * sc;
    }

    const int bid  = blockIdx.x;       // 2048
    const int r    = bid >> 2;         // image row
    const int col0 = (bid & 3) * 128;  // 128-col pixel tile

    // acc[msub(oc 16-blk)][n(pix 8-blk)][e] : D[oc][pix]
    float acc[2][8][4];
    #pragma unroll
    for (int m = 0; m < 2; ++m)
        #pragma unroll
        for (int n = 0; n < 8; ++n)
            #pragma unroll
            for (int e = 0; e < 4; ++e) acc[m][n][e] = 0.f;

    // ldmatrix lane geometry
    const int jj = lane >> 3, rr = lane & 7;
    const int a_row_l = ((jj & 1) << 3) + rr;
    const int a_col_l = (jj >> 1) << 4;
    const int b_row_l = ((jj >> 1) << 3) + rr;
    const int b_col_l = (jj & 1) << 4;

    // ---- prologue: async-prefetch W group 0 (taps 0..2, 48 KB) ----
    {
        const uint32_t d = smb + WGRP;
        #pragma unroll
        for (int p = 0; p < 12; ++p)
            cpasync16(d + (tid + p*256)*16, (const char*)Wb + (tid + p*256)*16);
        cpcommit();
    }

    // ---- persistent pixel tiles (fp16): buffer row i <-> image col col0-1+i, i in [0,130) ----
    #pragma unroll
    for (int dy = 0; dy < 3; ++dy) {
        int srow = r + dy - 1;
        srow = (srow < 0) ? -srow : ((srow > Hh-1) ? (2*Hh-2 - srow) : srow);
        const float* xrow = x + (size_t)srow * Ww;
        #pragma unroll
        for (int ii = 0; ii < 5; ++ii) {
            const int ipix = lane + 32*ii;
            if (ipix < 130) {
                int cc = col0 - 1 + ipix;
                cc = (cc < 0) ? -cc : ((cc > Ww-1) ? (2*Ww-2 - cc) : cc);
                float v[8];
                #pragma unroll
                for (int j = 0; j < 8; ++j)
                    v[j] = __ldg(xrow + (size_t)(w*8 + j) * HWSZ + cc);
                uint32_t hw4[4];
                #pragma unroll
                for (int q = 0; q < 4; ++q) {
                    __half2 hp = __floats2half2_rn(v[2*q], v[2*q+1]);
                    hw4[q] = *(uint32_t*)&hp;
                }
                const uint32_t off = SWZ((uint32_t)(ipix*128 + w*16));
                *(uint4*)(sm + ABUF(dy) + off) = make_uint4(hw4[0],hw4[1],hw4[2],hw4[3]);
            }
        }
    }

    // ---- main loop over 3 dy groups x 3 taps; only 5 CTA barriers total ----
    #pragma unroll
    for (int dyg = 0; dyg < 3; ++dyg) {
        if (dyg > 0) {
            __syncthreads();             // all warps done reading previous W group
            const uint32_t d = smb + WGRP;
            const char* src = (const char*)Wb + dyg*3*16384;
            #pragma unroll
            for (int p = 0; p < 12; ++p)
                cpasync16(d + (tid + p*256)*16, src + (tid + p*256)*16);
            cpcommit();
        }
        cpwait<0>();                     // W group landed
        __syncthreads();                 // W (+ A staging at dyg=0) visible everywhere

        const uint32_t ab = smb + ABUF(dyg);

        #pragma unroll
        for (int tap = 0; tap < 3; ++tap) {
            const int rowoff  = tap;     // dx+1
            const uint32_t wb = smb + WGRP + tap*16384;

            #pragma unroll
            for (int ks = 0; ks < 4; ++ks) {
                const int kbyte = ks*32;
                uint32_t bp[16];         // pixel B-frags: 64 pix = 4 ldsm4
                #pragma unroll
                for (int np = 0; np < 4; ++np) {
                    const int prow = wpix*64 + np*16 + b_row_l + rowoff;
                    const uint32_t poff = SWZ((uint32_t)(prow*128 + kbyte + b_col_l));
                    ldsm4(ab + poff, bp[np*4+0], bp[np*4+1], bp[np*4+2], bp[np*4+3]);
                }
                #pragma unroll
                for (int msub = 0; msub < 2; ++msub) {
                    const int wrow = woc*32 + msub*16 + a_row_l;
                    const uint32_t woff = SWZ((uint32_t)(wrow*128 + kbyte + a_col_l));
                    uint32_t ah[4];
                    ldsm4(wb + woff, ah[0], ah[1], ah[2], ah[3]);
                    #pragma unroll
                    for (int n = 0; n < 8; ++n)
                        hmma(acc[msub][n], ah[0],ah[1],ah[2],ah[3],
                             bp[n*2], bp[n*2+1]);
                }
            }
        }
    }

    // ---- epilogue: BN + LeakyReLU + mask, 2 consecutive pixels per lane (64b IO) ----
    const int pixc = (lane & 3) << 1;
    const int ocr  = lane >> 2;
    #pragma unroll
    for (int msub = 0; msub < 2; ++msub) {
        #pragma unroll
        for (int n = 0; n < 8; ++n) {
            const int pix = r*Ww + col0 + wpix*64 + n*8 + pixc;
            #pragma unroll
            for (int h = 0; h < 2; ++h) {
                const int oc = woc*32 + msub*16 + ocr + h*8;
                const float sc = s_scale[oc];
                const float sh = s_shift[oc];
                const int base = oc*HWSZ + pix;
                const int2 m2 = *(const int2*)(mask + base);
                float y0 = fmaf(acc[msub][n][h*2+0], sc, sh);
                float y1 = fmaf(acc[msub][n][h*2+1], sc, sh);
                y0 = (y0 >= 0.f) ? y0 : 0.01f * y0;
                y1 = (y1 >= 0.f) ? y1 : 0.01f * y1;
                float2 rv;
                rv.x = y0 * (float)m2.x;
                rv.y = y1 * (float)m2.y;
                *(float2*)(out + base) = rv;
            }
        }
    }
}

extern "C" void kernel_launch(void* const* d_in, const int* in_sizes, int n_in,
                              void* d_out, int out_size)
{
    const float* x     = (const float*)d_in[0];
    const float* Wt    = (const float*)d_in[1];
    const float* gamma = (const float*)d_in[2];
    const float* beta  = (const float*)d_in[3];
    const float* mean  = (const float*)d_in[4];
    const float* var   = (const float*)d_in[5];
    const int*   mask  = (const int*)d_in[6];
    float*       out   = (float*)d_out;

    cudaFuncSetAttribute(conv_mma_f16, cudaFuncAttributeMaxDynamicSharedMemorySize, SMEM_TOTAL);

    prep_w<<<(NT*KOC*CIN + 255)/256, 256>>>(Wt);
    conv_mma_f16<<<2048, 256, SMEM_TOTAL>>>(x, gamma, beta, mean, var, mask, out);
}

// round 15
// speedup vs baseline: 1.0419x; 1.0419x over previous
#include <cuda_runtime.h>
#include <cuda_fp16.h>
#include <cstdint>

#define Hh 512
#define Ww 512
#define CIN 64
#define KOC 128
#define HWSZ (Hh*Ww)
#define NT 9

#define SWZ(o) ((o) ^ ((((uint32_t)(o))>>3)&0x70))

// ---- dynamic smem layout (101 KB -> 2 CTAs/SM) ----
#define SCL    0
#define SHF    512
#define ABASE  1024
#define AROWS  136
#define ABUFSZ (AROWS*128)                   // 17408
#define ABUF(dy) (ABASE + (dy)*ABUFSZ)       // 3 buffers (dy 0..2), fp16 pixels
#define WBASE  (ABASE + 3*ABUFSZ)            // 53248
#define WBUF(s) (WBASE + (s)*16384)          // 3-slot W ring, fp16
#define SMEM_TOTAL (WBASE + 3*16384)         // 102400

__device__ __align__(16) unsigned char Wb[NT*16384];   // pre-swizzled fp16 W tiles

static __device__ __forceinline__ uint32_t s2u(const void* p){
    uint32_t a;
    asm("{ .reg .u64 t; cvta.to.shared.u64 t, %1; cvt.u32.u64 %0, t; }":"=r"(a):"l"(p));
    return a;
}
static __device__ __forceinline__ void ldsm4(uint32_t addr,
        uint32_t &r0, uint32_t &r1, uint32_t &r2, uint32_t &r3){
    asm volatile("ldmatrix.sync.aligned.m8n8.x4.shared.b16 {%0,%1,%2,%3}, [%4];"
        : "=r"(r0),"=r"(r1),"=r"(r2),"=r"(r3) : "r"(addr));
}
static __device__ __forceinline__ void hmma(float* c,
        uint32_t a0,uint32_t a1,uint32_t a2,uint32_t a3,
        uint32_t b0,uint32_t b1){
    asm volatile("mma.sync.aligned.m16n8k16.row.col.f32.f16.f16.f32 "
        "{%0,%1,%2,%3}, {%4,%5,%6,%7}, {%8,%9}, {%0,%1,%2,%3};"
        : "+f"(c[0]),"+f"(c[1]),"+f"(c[2]),"+f"(c[3])
        : "r"(a0),"r"(a1),"r"(a2),"r"(a3),"r"(b0),"r"(b1));
}
static __device__ __forceinline__ void cpasync16(uint32_t daddr, const void* g){
    asm volatile("cp.async.cg.shared.global [%0], [%1], 16;" :: "r"(daddr), "l"(g) : "memory");
}
static __device__ __forceinline__ void cpcommit(){
    asm volatile("cp.async.commit_group;" ::: "memory");
}
template<int N> static __device__ __forceinline__ void cpwait(){
    asm volatile("cp.async.wait_group %0;" :: "n"(N) : "memory");
}

// ---------- prep: W -> fp16, pre-swizzled K-major SW128 tiles (rows = oc) ----------
__global__ void prep_w(const float* __restrict__ Wt){
    int idx = blockIdx.x * blockDim.x + threadIdx.x;   // 9*128*64
    if (idx >= NT*KOC*CIN) return;
    int t   = idx >> 13;
    int rem = idx & 8191;
    int n   = rem >> 6;
    int kk  = rem & 63;
    float v = Wt[(n*CIN + kk)*9 + t];
    uint32_t off = SWZ((uint32_t)(n*128 + kk*2));
    *(__half*)(Wb + t*16384 + off) = __float2half_rn(v);
}

// ---------- main fused kernel: fp16 1-pass, M=oc(128) x N=pix(128), 3-slot W ring ----------
__global__ void __launch_bounds__(256,2)
conv_mma_f16(const float* __restrict__ x,
             const float* __restrict__ gamma, const float* __restrict__ beta,
             const float* __restrict__ mean,  const float* __restrict__ var,
             const int*   __restrict__ mask,  float* __restrict__ out)
{
    extern __shared__ __align__(1024) char sm[];
    const uint32_t smb = s2u(sm);

    const int tid  = threadIdx.x;
    const int w    = tid >> 5;
    const int lane = tid & 31;
    const int wpix = w >> 2;           // 0..1 : pixel offset wpix*64 (N dim)
    const int woc  = w & 3;            // 0..3 : oc offset woc*32   (M dim)

    float* s_scale = (float*)(sm + SCL);
    float* s_shift = (float*)(sm + SHF);
    if (tid < KOC) {
        float sc = gamma[tid] * rsqrtf(var[tid] + 1e-5f);
        s_scale[tid] = sc;
        s_shift[tid] = beta[tid] - mean[tid] * sc;
    }

    const int bid  = blockIdx.x;       // 2048
    const int r    = bid >> 2;         // image row
    const int col0 = (bid & 3) * 128;  // 128-col pixel tile

    // acc[msub(oc 16-blk)][n(pix 8-blk)][e] : D[oc][pix]
    float acc[2][8][4];
    #pragma unroll
    for (int m = 0; m < 2; ++m)
        #pragma unroll
        for (int n = 0; n < 8; ++n)
            #pragma unroll
            for (int e = 0; e < 4; ++e) acc[m][n][e] = 0.f;

    // ldmatrix lane geometry
    const int jj = lane >> 3, rr = lane & 7;
    const int a_row_l = ((jj & 1) << 3) + rr;
    const int a_col_l = (jj >> 1) << 4;
    const int b_row_l = ((jj >> 1) << 3) + rr;
    const int b_col_l = (jj & 1) << 4;

    // ---- prologue: async-prefetch W taps 0 and 1 (separate commit groups) ----
    #pragma unroll
    for (int c0 = 0; c0 < 2; ++c0) {
        const uint32_t d = smb + WBUF(c0);
        const char* src = (const char*)Wb + c0*16384;
        #pragma unroll
        for (int p = 0; p < 4; ++p)
            cpasync16(d + (tid + p*256)*16, src + (tid + p*256)*16);
        cpcommit();
    }

    // ---- persistent pixel tiles (fp16): buffer row i <-> image col col0-1+i, i in [0,130) ----
    #pragma unroll
    for (int dy = 0; dy < 3; ++dy) {
        int srow = r + dy - 1;
        srow = (srow < 0) ? -srow : ((srow > Hh-1) ? (2*Hh-2 - srow) : srow);
        const float* xrow = x + (size_t)srow * Ww;
        #pragma unroll
        for (int ii = 0; ii < 5; ++ii) {
            const int ipix = lane + 32*ii;
            if (ipix < 130) {
                int cc = col0 - 1 + ipix;
                cc = (cc < 0) ? -cc : ((cc > Ww-1) ? (2*Ww-2 - cc) : cc);
                float v[8];
                #pragma unroll
                for (int j = 0; j < 8; ++j)
                    v[j] = __ldg(xrow + (size_t)(w*8 + j) * HWSZ + cc);
                uint32_t hw4[4];
                #pragma unroll
                for (int q = 0; q < 4; ++q) {
                    __half2 hp = __floats2half2_rn(v[2*q], v[2*q+1]);
                    hw4[q] = *(uint32_t*)&hp;
                }
                const uint32_t off = SWZ((uint32_t)(ipix*128 + w*16));
                *(uint4*)(sm + ABUF(dy) + off) = make_uint4(hw4[0],hw4[1],hw4[2],hw4[3]);
            }
        }
    }

    // ---- main loop: 9 taps, ONE barrier per tap, 2-tap prefetch distance ----
    for (int ch = 0; ch < NT; ++ch) {
        if (ch < NT-1) cpwait<1>();      // W(ch) landed (one newer group may be in flight)
        else           cpwait<0>();      // last tap: drain all
        __syncthreads();                 // W(ch) visible CTA-wide; all warps past tap ch-1
                                         // (slot (ch+2)%3, written below, was read at tap ch-1)

        if (ch + 2 < NT) {               // prefetch W(ch+2) into ring slot (ch+2)%3
            const uint32_t d = smb + WBUF((ch+2) % 3);
            const char* src = (const char*)Wb + (ch+2)*16384;
            #pragma unroll
            for (int p = 0; p < 4; ++p)
                cpasync16(d + (tid + p*256)*16, src + (tid + p*256)*16);
            cpcommit();
        }

        const int dyi    = ch / 3;
        const int rowoff = ch - dyi*3;   // dx+1, applies to pixel rows (B side)
        const uint32_t wb = smb + WBUF(ch % 3);
        const uint32_t ab = smb + ABUF(dyi);

        #pragma unroll
        for (int ks = 0; ks < 4; ++ks) {
            const int kbyte = ks*32;
            uint32_t bp[16];             // pixel B-frags: 64 pix = 4 ldsm4
            #pragma unroll
            for (int np = 0; np < 4; ++np) {
                const int prow = wpix*64 + np*16 + b_row_l + rowoff;
                const uint32_t poff = SWZ((uint32_t)(prow*128 + kbyte + b_col_l));
                ldsm4(ab + poff, bp[np*4+0], bp[np*4+1], bp[np*4+2], bp[np*4+3]);
            }
            #pragma unroll
            for (int msub = 0; msub < 2; ++msub) {
                const int wrow = woc*32 + msub*16 + a_row_l;
                const uint32_t woff = SWZ((uint32_t)(wrow*128 + kbyte + a_col_l));
                uint32_t ah[4];
                ldsm4(wb + woff, ah[0], ah[1], ah[2], ah[3]);
                #pragma unroll
                for (int n = 0; n < 8; ++n)
                    hmma(acc[msub][n], ah[0],ah[1],ah[2],ah[3],
                         bp[n*2], bp[n*2+1]);
            }
        }
    }

    // ---- epilogue: BN + LeakyReLU + mask, 2 consecutive pixels per lane (64b IO) ----
    const int pixc = (lane & 3) << 1;
    const int ocr  = lane >> 2;
    #pragma unroll
    for (int msub = 0; msub < 2; ++msub) {
        #pragma unroll
        for (int n = 0; n < 8; ++n) {
            const int pix = r*Ww + col0 + wpix*64 + n*8 + pixc;
            #pragma unroll
            for (int h = 0; h < 2; ++h) {
                const int oc = woc*32 + msub*16 + ocr + h*8;
                const float sc = s_scale[oc];
                const float sh = s_shift[oc];
                const int base = oc*HWSZ + pix;
                const int2 m2 = *(const int2*)(mask + base);
                float y0 = fmaf(acc[msub][n][h*2+0], sc, sh);
                float y1 = fmaf(acc[msub][n][h*2+1], sc, sh);
                y0 = (y0 >= 0.f) ? y0 : 0.01f * y0;
                y1 = (y1 >= 0.f) ? y1 : 0.01f * y1;
                float2 rv;
                rv.x = y0 * (float)m2.x;
                rv.y = y1 * (float)m2.y;
                *(float2*)(out + base) = rv;
            }
        }
    }
}

extern "C" void kernel_launch(void* const* d_in, const int* in_sizes, int n_in,
                              void* d_out, int out_size)
{
    const float* x     = (const float*)d_in[0];
    const float* Wt    = (const float*)d_in[1];
    const float* gamma = (const float*)d_in[2];
    const float* beta  = (const float*)d_in[3];
    const float* mean  = (const float*)d_in[4];
    const float* var   = (const float*)d_in[5];
    const int*   mask  = (const int*)d_in[6];
    float*       out   = (float*)d_out;

    cudaFuncSetAttribute(conv_mma_f16, cudaFuncAttributeMaxDynamicSharedMemorySize, SMEM_TOTAL);

    prep_w<<<(NT*KOC*CIN + 255)/256, 256>>>(Wt);
    conv_mma_f16<<<2048, 256, SMEM_TOTAL>>>(x, gamma, beta, mean, var, mask, out);
}

// round 16
// speedup vs baseline: 1.1199x; 1.0749x over previous
#include <cuda_runtime.h>
#include <cuda_fp16.h>
#include <cstdint>

#define Hh 512
#define Ww 512
#define CIN 64
#define KOC 128
#define HWSZ (Hh*Ww)
#define NT 9

#define SWZ(o) ((o) ^ ((((uint32_t)(o))>>3)&0x70))

// ---- dynamic smem layout (84 KB -> 2 CTAs/SM), identical to R12 ----
#define SCL    0
#define SHF    512
#define ABASE  1024
#define AROWS  136
#define ABUFSZ (AROWS*128)                   // 17408
#define ABUF(dy) (ABASE + (dy)*ABUFSZ)       // 3 buffers (dy 0..2), fp16 pixels
#define WBASE  (ABASE + 3*ABUFSZ)            // 53248
#define WBUF(b) (WBASE + (b)*16384)          // double-buffered W, fp16
#define SMEM_TOTAL (WBASE + 2*16384)         // 86016

#define XT_TILE 16640                        // 130 px rows x 128 B, swizzled fp16

__device__ __align__(16) unsigned char Wb[NT*16384];          // pre-swizzled fp16 W tiles
__device__ __align__(16) unsigned char Xt[512*4*XT_TILE];     // pre-swizzled fp16 x tiles (34 MB)

static __device__ __forceinline__ uint32_t s2u(const void* p){
    uint32_t a;
    asm("{ .reg .u64 t; cvta.to.shared.u64 t, %1; cvt.u32.u64 %0, t; }":"=r"(a):"l"(p));
    return a;
}
static __device__ __forceinline__ void ldsm4(uint32_t addr,
        uint32_t &r0, uint32_t &r1, uint32_t &r2, uint32_t &r3){
    asm volatile("ldmatrix.sync.aligned.m8n8.x4.shared.b16 {%0,%1,%2,%3}, [%4];"
        : "=r"(r0),"=r"(r1),"=r"(r2),"=r"(r3) : "r"(addr));
}
static __device__ __forceinline__ void hmma(float* c,
        uint32_t a0,uint32_t a1,uint32_t a2,uint32_t a3,
        uint32_t b0,uint32_t b1){
    asm volatile("mma.sync.aligned.m16n8k16.row.col.f32.f16.f16.f32 "
        "{%0,%1,%2,%3}, {%4,%5,%6,%7}, {%8,%9}, {%0,%1,%2,%3};"
        : "+f"(c[0]),"+f"(c[1]),"+f"(c[2]),"+f"(c[3])
        : "r"(a0),"r"(a1),"r"(a2),"r"(a3),"r"(b0),"r"(b1));
}
static __device__ __forceinline__ void cpasync16(uint32_t daddr, const void* g){
    asm volatile("cp.async.cg.shared.global [%0], [%1], 16;" :: "r"(daddr), "l"(g) : "memory");
}
static __device__ __forceinline__ void cpcommit(){
    asm volatile("cp.async.commit_group;" ::: "memory");
}
template<int N> static __device__ __forceinline__ void cpwait(){
    asm volatile("cp.async.wait_group %0;" :: "n"(N) : "memory");
}

// ---------- prep: W -> fp16, pre-swizzled K-major SW128 tiles (rows = oc) ----------
__global__ void prep_w(const float* __restrict__ Wt){
    int idx = blockIdx.x * blockDim.x + threadIdx.x;   // 9*128*64
    if (idx >= NT*KOC*CIN) return;
    int t   = idx >> 13;
    int rem = idx & 8191;
    int n   = rem >> 6;
    int kk  = rem & 63;
    float v = Wt[(n*CIN + kk)*9 + t];
    uint32_t off = SWZ((uint32_t)(n*128 + kk*2));
    *(__half*)(Wb + t*16384 + off) = __float2half_rn(v);
}

// ---------- prep: x -> fp16, pre-swizzled 130x128B tiles per (row, col-tile) ----------
// thread = (((row*4 + tile)*8) + w)*130 + ipix ; each writes one 16B chunk (8 channels)
__global__ void prep_x(const float* __restrict__ x){
    int idx = blockIdx.x * blockDim.x + threadIdx.x;
    if (idx >= 512*4*8*130) return;
    const int ipix = idx % 130;
    int t2   = idx / 130;
    const int w    = t2 & 7;
    t2 >>= 3;
    const int tile = t2 & 3;
    const int row  = t2 >> 2;

    int cc = tile*128 - 1 + ipix;
    cc = (cc < 0) ? -cc : ((cc > Ww-1) ? (2*Ww-2 - cc) : cc);
    const float* xp = x + (size_t)row * Ww + cc;
    uint32_t hw4[4];
    #pragma unroll
    for (int q = 0; q < 4; ++q) {
        float a = xp[(size_t)(w*8 + 2*q    ) * HWSZ];
        float b = xp[(size_t)(w*8 + 2*q + 1) * HWSZ];
        __half2 hp = __floats2half2_rn(a, b);
        hw4[q] = *(uint32_t*)&hp;
    }
    const uint32_t off = SWZ((uint32_t)(ipix*128 + w*16));
    *(uint4*)(Xt + (size_t)(row*4 + tile)*XT_TILE + off) = make_uint4(hw4[0],hw4[1],hw4[2],hw4[3]);
}

// ---------- main fused kernel: fp16 1-pass, M=oc(128) x N=pix(128), 2 CTAs/SM ----------
__global__ void __launch_bounds__(256,2)
conv_mma_f16(const float* __restrict__ gamma, const float* __restrict__ beta,
             const float* __restrict__ mean,  const float* __restrict__ var,
             const int*   __restrict__ mask,  float* __restrict__ out)
{
    extern __shared__ __align__(1024) char sm[];
    const uint32_t smb = s2u(sm);

    const int tid  = threadIdx.x;
    const int w    = tid >> 5;
    const int lane = tid & 31;
    const int wpix = w >> 2;           // 0..1 : pixel offset wpix*64 (N dim)
    const int woc  = w & 3;            // 0..3 : oc offset woc*32   (M dim)

    float* s_scale = (float*)(sm + SCL);
    float* s_shift = (float*)(sm + SHF);
    if (tid < KOC) {
        float sc = gamma[tid] * rsqrtf(var[tid] + 1e-5f);
        s_scale[tid] = sc;
        s_shift[tid] = beta[tid] - mean[tid] * sc;
    }

    const int bid  = blockIdx.x;       // 2048
    const int r    = bid >> 2;         // image row
    const int tile = bid & 3;
    const int col0 = tile * 128;       // 128-col pixel tile

    // acc[msub(oc 16-blk)][n(pix 8-blk)][e] : D[oc][pix]
    float acc[2][8][4];
    #pragma unroll
    for (int m = 0; m < 2; ++m)
        #pragma unroll
        for (int n = 0; n < 8; ++n)
            #pragma unroll
            for (int e = 0; e < 4; ++e) acc[m][n][e] = 0.f;

    // ldmatrix lane geometry
    const int jj = lane >> 3, rr = lane & 7;
    const int a_row_l = ((jj & 1) << 3) + rr;
    const int a_col_l = (jj >> 1) << 4;
    const int b_row_l = ((jj >> 1) << 3) + rr;
    const int b_col_l = (jj & 1) << 4;

    // ---- prologue: async-prefetch W tap 0 (group 0) ----
    {
        const uint32_t d = smb + WBUF(0);
        #pragma unroll
        for (int p = 0; p < 4; ++p)
            cpasync16(d + (tid + p*256)*16, (const char*)Wb + (tid + p*256)*16);
        cpcommit();
    }

    // ---- A-staging: pure cp.async of pre-swizzled fp16 tiles (group 1) ----
    #pragma unroll
    for (int dy = 0; dy < 3; ++dy) {
        int srow = r + dy - 1;
        srow = (srow < 0) ? -srow : ((srow > Hh-1) ? (2*Hh-2 - srow) : srow);
        const char* src = (const char*)Xt + (size_t)(srow*4 + tile)*XT_TILE;
        const uint32_t d = smb + ABUF(dy);
        #pragma unroll
        for (int p = 0; p < 5; ++p) {
            const int chunk = tid + p*256;           // 16B chunks, 1040 total
            if (chunk < XT_TILE/16)
                cpasync16(d + chunk*16, src + chunk*16);
        }
    }
    cpcommit();

    // ---- main loop over 9 taps, W double-buffered via cp.async (R12 cadence) ----
    for (int ch = 0; ch < NT; ++ch) {
        __syncthreads();     // all reads of WBUF((ch+1)&1) from tap ch-1 complete

        if (ch + 1 < NT) {   // prefetch W(ch+1) into the other buffer
            const uint32_t d = smb + WBUF((ch+1) & 1);
            const char* sh = (const char*)Wb + (ch+1)*16384;
            #pragma unroll
            for (int p = 0; p < 4; ++p)
                cpasync16(d + (tid + p*256)*16, sh + (tid + p*256)*16);
            cpcommit();
            cpwait<1>();     // W(ch) (+ A at ch=0) has landed
        } else {
            cpwait<0>();
        }
        __syncthreads();     // W(ch) (+ pixel staging at ch=0) visible to all warps

        const int dyi    = ch / 3;
        const int rowoff = (ch % 3);         // dx+1, applies to pixel rows (B side)
        const uint32_t wb = smb + WBUF(ch & 1);
        const uint32_t ab = smb + ABUF(dyi);

        #pragma unroll
        for (int ks = 0; ks < 4; ++ks) {
            const int kbyte = ks*32;
            uint32_t bp[16];                 // pixel B-frags: 64 pix = 4 ldsm4
            #pragma unroll
            for (int np = 0; np < 4; ++np) {
                const int prow = wpix*64 + np*16 + b_row_l + rowoff;
                const uint32_t poff = SWZ((uint32_t)(prow*128 + kbyte + b_col_l));
                ldsm4(ab + poff, bp[np*4+0], bp[np*4+1], bp[np*4+2], bp[np*4+3]);
            }
            #pragma unroll
            for (int msub = 0; msub < 2; ++msub) {
                const int wrow = woc*32 + msub*16 + a_row_l;
                const uint32_t woff = SWZ((uint32_t)(wrow*128 + kbyte + a_col_l));
                uint32_t ah[4];
                ldsm4(wb + woff, ah[0], ah[1], ah[2], ah[3]);
                #pragma unroll
                for (int n = 0; n < 8; ++n)
                    hmma(acc[msub][n], ah[0],ah[1],ah[2],ah[3],
                         bp[n*2], bp[n*2+1]);
            }
        }
    }

    // ---- epilogue: BN + LeakyReLU + mask, 2 consecutive pixels per lane (64b IO) ----
    const int pixc = (lane & 3) << 1;
    const int ocr  = lane >> 2;
    #pragma unroll
    for (int msub = 0; msub < 2; ++msub) {
        #pragma unroll
        for (int n = 0; n < 8; ++n) {
            const int pix = r*Ww + col0 + wpix*64 + n*8 + pixc;
            #pragma unroll
            for (int h = 0; h < 2; ++h) {
                const int oc = woc*32 + msub*16 + ocr + h*8;
                const float sc = s_scale[oc];
                const float sh = s_shift[oc];
                const int base = oc*HWSZ + pix;
                const int2 m2 = *(const int2*)(mask + base);
                float y0 = fmaf(acc[msub][n][h*2+0], sc, sh);
                float y1 = fmaf(acc[msub][n][h*2+1], sc, sh);
                y0 = (y0 >= 0.f) ? y0 : 0.01f * y0;
                y1 = (y1 >= 0.f) ? y1 : 0.01f * y1;
                float2 rv;
                rv.x = y0 * (float)m2.x;
                rv.y = y1 * (float)m2.y;
                *(float2*)(out + base) = rv;
            }
        }
    }
}

extern "C" void kernel_launch(void* const* d_in, const int* in_sizes, int n_in,
                              void* d_out, int out_size)
{
    const float* x     = (const float*)d_in[0];
    const float* Wt    = (const float*)d_in[1];
    const float* gamma = (const float*)d_in[2];
    const float* beta  = (const float*)d_in[3];
    const float* mean  = (const float*)d_in[4];
    const float* var   = (const float*)d_in[5];
    const int*   mask  = (const int*)d_in[6];
    float*       out   = (float*)d_out;

    cudaFuncSetAttribute(conv_mma_f16, cudaFuncAttributeMaxDynamicSharedMemorySize, SMEM_TOTAL);

    prep_w<<<(NT*KOC*CIN + 255)/256, 256>>>(Wt);
    prep_x<<<(512*4*8*130 + 255)/256, 256>>>(x);
    conv_mma_f16<<<2048, 256, SMEM_TOTAL>>>(gamma, beta, mean, var, mask, out);
}